// round 8
// baseline (speedup 1.0000x reference)
#include <cuda_runtime.h>
#include <cuda_bf16.h>

#define B_TOT 32768
#define T_LEN 200
#define DE    6
#define NIV   8
#define H     128
#define DIN   46
#define NPAIR (B_TOT/2)
#define UNITS 64
#define ROWF  36
#define GRP   8
#define UPG   8
#define TD    (T_LEN*DE)
#define RUNS  (NPAIR/4)

typedef unsigned long long ull;

__device__ unsigned g_run_ctr;

static __device__ __forceinline__ ull pk2(float lo, float hi) {
    ull r; asm("mov.b64 %0,{%1,%2};" : "=l"(r) : "f"(lo), "f"(hi)); return r;
}
static __device__ __forceinline__ void upk2(ull v, float& lo, float& hi) {
    asm("mov.b64 {%0,%1},%2;" : "=f"(lo), "=f"(hi) : "l"(v));
}
static __device__ __forceinline__ ull fma2(ull a, ull b, ull c) {
    ull d; asm("fma.rn.f32x2 %0,%1,%2,%3;" : "=l"(d) : "l"(a), "l"(b), "l"(c)); return d;
}
static __device__ __forceinline__ ull mul2(ull a, ull b) {
    ull d; asm("mul.rn.f32x2 %0,%1,%2;" : "=l"(d) : "l"(a), "l"(b)); return d;
}
static __device__ __forceinline__ ull add2(ull a, ull b) {
    ull d; asm("add.rn.f32x2 %0,%1,%2;" : "=l"(d) : "l"(a), "l"(b)); return d;
}
static __device__ __forceinline__ ull relu2(ull a) {
    float lo, hi; upk2(a, lo, hi);
    lo = fmaxf(lo, 0.f); hi = fmaxf(hi, 0.f);
    return pk2(lo, hi);
}
static __device__ __forceinline__ ull dupf(float v) { return pk2(v, v); }

static __device__ __forceinline__ float hsum(ull v) {
    float lo, hi; upk2(v, lo, hi); return lo + hi;
}
static __device__ __forceinline__ float bfly3(float s) {
    s += __shfl_xor_sync(0xFFFFFFFFu, s, 4);
    s += __shfl_xor_sync(0xFFFFFFFFu, s, 8);
    s += __shfl_xor_sync(0xFFFFFFFFu, s, 16);
    return s;
}
static __device__ __forceinline__ float red8(ull v) { return bfly3(hsum(v)); }

static __device__ __forceinline__ void mlp2(const float* __restrict__ tab, int g,
    const ull* __restrict__ i6a, const ull* __restrict__ i8a, ull Ea, ull nua,
    const ull* __restrict__ i6b, const ull* __restrict__ i8b, ull Eb, ull nub,
    ull* __restrict__ accA, ull* __restrict__ accB)
{
    const int base = g * UPG;
#pragma unroll 4
    for (int i = 0; i < UPG; ++i) {
        int uu = base + ((i + g) & (UPG - 1));   // stagger: conflict-free banks
        const ulonglong2* r = reinterpret_cast<const ulonglong2*>(tab + uu * ROWF);
        ulonglong2 r0 = r[0], r1 = r[1], r2 = r[2], r3 = r[3], r4 = r[4];
        ulonglong2 r5 = r[5], r6 = r[6], r7 = r[7], r8 = r[8];

        ull pa = fma2(r7.y, Ea, r7.x);  pa = fma2(r8.x, nua, pa);
        pa = fma2(r0.x, i6a[0], pa);    pa = fma2(r0.y, i6a[1], pa);
        pa = fma2(r1.x, i6a[2], pa);    pa = fma2(r1.y, i6a[3], pa);
        pa = fma2(r2.x, i6a[4], pa);    pa = fma2(r2.y, i6a[5], pa);
        ull qa = mul2(r3.x, i8a[0]);    qa = fma2(r3.y, i8a[1], qa);
        qa = fma2(r4.x, i8a[2], qa);    qa = fma2(r4.y, i8a[3], qa);
        qa = fma2(r5.x, i8a[4], qa);    qa = fma2(r5.y, i8a[5], qa);
        qa = fma2(r6.x, i8a[6], qa);    qa = fma2(r6.y, i8a[7], qa);
        ull ra = mul2(relu2(add2(pa, qa)), r8.y);

        ull pb = fma2(r7.y, Eb, r7.x);  pb = fma2(r8.x, nub, pb);
        pb = fma2(r0.x, i6b[0], pb);    pb = fma2(r0.y, i6b[1], pb);
        pb = fma2(r1.x, i6b[2], pb);    pb = fma2(r1.y, i6b[3], pb);
        pb = fma2(r2.x, i6b[4], pb);    pb = fma2(r2.y, i6b[5], pb);
        ull qb = mul2(r3.x, i8b[0]);    qb = fma2(r3.y, i8b[1], qb);
        qb = fma2(r4.x, i8b[2], qb);    qb = fma2(r4.y, i8b[3], qb);
        qb = fma2(r5.x, i8b[4], qb);    qb = fma2(r5.y, i8b[5], qb);
        qb = fma2(r6.x, i8b[6], qb);    qb = fma2(r6.y, i8b[7], qb);
        ull rb = mul2(relu2(add2(pb, qb)), r8.y);

        accA[0]  = fma2(r0.x, ra, accA[0]);   accB[0]  = fma2(r0.x, rb, accB[0]);
        accA[1]  = fma2(r0.y, ra, accA[1]);   accB[1]  = fma2(r0.y, rb, accB[1]);
        accA[2]  = fma2(r1.x, ra, accA[2]);   accB[2]  = fma2(r1.x, rb, accB[2]);
        accA[3]  = fma2(r1.y, ra, accA[3]);   accB[3]  = fma2(r1.y, rb, accB[3]);
        accA[4]  = fma2(r2.x, ra, accA[4]);   accB[4]  = fma2(r2.x, rb, accB[4]);
        accA[5]  = fma2(r2.y, ra, accA[5]);   accB[5]  = fma2(r2.y, rb, accB[5]);
        accA[6]  = fma2(r3.x, ra, accA[6]);   accB[6]  = fma2(r3.x, rb, accB[6]);
        accA[7]  = fma2(r3.y, ra, accA[7]);   accB[7]  = fma2(r3.y, rb, accB[7]);
        accA[8]  = fma2(r4.x, ra, accA[8]);   accB[8]  = fma2(r4.x, rb, accB[8]);
        accA[9]  = fma2(r4.y, ra, accA[9]);   accB[9]  = fma2(r4.y, rb, accB[9]);
        accA[10] = fma2(r5.x, ra, accA[10]);  accB[10] = fma2(r5.x, rb, accB[10]);
        accA[11] = fma2(r5.y, ra, accA[11]);  accB[11] = fma2(r5.y, rb, accB[11]);
        accA[12] = fma2(r6.x, ra, accA[12]);  accB[12] = fma2(r6.x, rb, accB[12]);
        accA[13] = fma2(r6.y, ra, accA[13]);  accB[13] = fma2(r6.y, rb, accB[13]);
    }
}

__global__ void reset_ctr_kernel() { g_run_ctr = 0u; }

__global__ void __launch_bounds__(128, 3) visco_kernel(
    const float* __restrict__ e,   const float* __restrict__ edot,
    const float* __restrict__ Eg,  const float* __restrict__ nug,
    const float* __restrict__ We1, const float* __restrict__ be1,
    const float* __restrict__ We2,
    const float* __restrict__ Wd1, const float* __restrict__ bd1,
    const float* __restrict__ Wd2,
    const float* __restrict__ WE,  const float* __restrict__ bE,
    const float* __restrict__ Wnu, const float* __restrict__ bnu,
    float* __restrict__ out)
{
    __shared__ __align__(16) float sE2[UNITS * ROWF];
    __shared__ __align__(16) float sD2[UNITS * ROWF];

    {   // build row-pair-interleaved derived tables (thread h builds row h of both)
        int h = threadIdx.x;
        int u = h >> 1, par = h & 1;
        float* dE = sE2 + u * ROWF + par;
        float* dD = sD2 + u * ROWF + par;

        const float* w1 = We1 + h * DIN;
#pragma unroll
        for (int j = 0; j < 14; ++j) dE[2 * j] = w1[j];
        float a = be1[h], bt = 0.f, gm = 0.f;
#pragma unroll
        for (int k = 0; k < 16; ++k) { float wm = w1[14 + k]; a += wm * bE[k];  bt += wm * WE[k]; }
#pragma unroll
        for (int k = 0; k < 16; ++k) { float wm = w1[30 + k]; a += wm * bnu[k]; gm += wm * Wnu[k]; }
        dE[28] = a; dE[30] = bt; dE[32] = gm;
        dE[34] = 2.f * (We2[h] + We2[H + h]);

        const float* w2 = Wd1 + h * DIN;
#pragma unroll
        for (int j = 0; j < 14; ++j) dD[2 * j] = -w2[j];
        a = bd1[h]; bt = 0.f; gm = 0.f;
#pragma unroll
        for (int k = 0; k < 16; ++k) { float wm = w2[14 + k]; a += wm * bE[k];  bt += wm * WE[k]; }
#pragma unroll
        for (int k = 0; k < 16; ++k) { float wm = w2[30 + k]; a += wm * bnu[k]; gm += wm * Wnu[k]; }
        dD[28] = a; dD[30] = bt; dD[32] = gm;
        dD[34] = 2.f * Wd2[h];
    }
    __syncthreads();

    const int lane = threadIdx.x & 31;
    const int pr   = lane & 3;                   // pair slot within warp
    const int g    = lane >> 2;                  // h-split group 0..7
    const ull SGN  = 0x8000000080000000ULL;

    for (;;) {
        unsigned run;
        if (lane == 0) run = atomicAdd(&g_run_ctr, 1u);
        run = __shfl_sync(0xFFFFFFFFu, run, 0);
        if (run >= RUNS) break;

        int p = (int)run * 4 + pr;
        size_t b0 = 2 * (size_t)p;

        ull E0d  = dupf(Eg[b0]),  E1d  = dupf(Eg[b0 + 1]);
        ull nu0d = dupf(nug[b0]), nu1d = dupf(nug[b0 + 1]);

        const float* pe0 = e    + b0 * TD;
        const float* pe1 = pe0  + TD;
        const float* pd0 = edot + b0 * TD;
        const float* pd1 = pd0  + TD;

        // xi as scalars (lo==hi invariant under the broadcast update)
        float xs0[NIV], xs1[NIV];
#pragma unroll
        for (int j = 0; j < NIV; ++j) { xs0[j] = 0.f; xs1[j] = 0.f; }

        float2 ea0 = *(const float2*)(pe0), ea1 = *(const float2*)(pe0 + 2), ea2 = *(const float2*)(pe0 + 4);
        float2 eb0 = *(const float2*)(pe1), eb1 = *(const float2*)(pe1 + 2), eb2 = *(const float2*)(pe1 + 4);
        float2 da0 = *(const float2*)(pd0), da1 = *(const float2*)(pd0 + 2), da2 = *(const float2*)(pd0 + 4);
        float2 db0 = *(const float2*)(pd1), db1 = *(const float2*)(pd1 + 2), db2 = *(const float2*)(pd1 + 4);

        for (int t = 0; t < T_LEN; ++t) {
            // ---- E-MLP inputs (e raw buffers consumed here) ----
            ull et0[6] = { dupf(ea0.x), dupf(ea0.y), dupf(ea1.x), dupf(ea1.y), dupf(ea2.x), dupf(ea2.y) };
            ull et1[6] = { dupf(eb0.x), dupf(eb0.y), dupf(eb1.x), dupf(eb1.y), dupf(eb2.x), dupf(eb2.y) };
            ull xi0p[NIV], xi1p[NIV];
#pragma unroll
            for (int j = 0; j < NIV; ++j) { xi0p[j] = dupf(xs0[j]); xi1p[j] = dupf(xs1[j]); }

            if (g == 1) {     // xi output (state entering this step)
                float* xo0 = out + (size_t)B_TOT * TD + b0 * (size_t)(T_LEN * NIV) + t * NIV;
                float* xo1 = xo0 + T_LEN * NIV;
#pragma unroll
                for (int k = 0; k < NIV; k += 2) {
                    *(float2*)(xo0 + k) = make_float2(xs0[k], xs0[k + 1]);
                    *(float2*)(xo1 + k) = make_float2(xs1[k], xs1[k + 1]);
                }
            }

            ull accA[14], accB[14];
#pragma unroll
            for (int j = 0; j < 14; ++j) { accA[j] = 0ULL; accB[j] = 0ULL; }
            mlp2(sE2, g, et0, xi0p, E0d, nu0d, et1, xi1p, E1d, nu1d, accA, accB);

            // seq partials (scalar, no shuffles); d reduced + broadcast
            float hE0[6], hE1[6];
            ull d0[8], d1[8];
#pragma unroll
            for (int j = 0; j < 6; ++j) { hE0[j] = hsum(accA[j]); hE1[j] = hsum(accB[j]); }
#pragma unroll
            for (int j = 0; j < 8; ++j) { d0[j] = dupf(red8(accA[6 + j])); d1[j] = dupf(red8(accB[6 + j])); }

            // ---- D-MLP inputs (edot raw buffers consumed here) ----
            ull ed0[6] = { dupf(da0.x) ^ SGN, dupf(da0.y) ^ SGN, dupf(da1.x) ^ SGN,
                           dupf(da1.y) ^ SGN, dupf(da2.x) ^ SGN, dupf(da2.y) ^ SGN };
            ull ed1[6] = { dupf(db0.x) ^ SGN, dupf(db0.y) ^ SGN, dupf(db1.x) ^ SGN,
                           dupf(db1.y) ^ SGN, dupf(db2.x) ^ SGN, dupf(db2.y) ^ SGN };

            // prefetch next step (raw buffers free now; ~half a step ahead of use)
            if (t + 1 < T_LEN) {
                int o = (t + 1) * DE;
                ea0 = *(const float2*)(pe0 + o); ea1 = *(const float2*)(pe0 + o + 2); ea2 = *(const float2*)(pe0 + o + 4);
                eb0 = *(const float2*)(pe1 + o); eb1 = *(const float2*)(pe1 + o + 2); eb2 = *(const float2*)(pe1 + o + 4);
                da0 = *(const float2*)(pd0 + o); da1 = *(const float2*)(pd0 + o + 2); da2 = *(const float2*)(pd0 + o + 4);
                db0 = *(const float2*)(pd1 + o); db1 = *(const float2*)(pd1 + o + 2); db2 = *(const float2*)(pd1 + o + 4);
            }

#pragma unroll
            for (int j = 0; j < 14; ++j) { accA[j] = 0ULL; accB[j] = 0ULL; }
            mlp2(sD2, g, ed0, d0, E0d, nu0d, ed1, d1, E1d, nu1d, accA, accB);

            // stress: single butterfly over combined E+D partials
            float st0[6], st1[6];
#pragma unroll
            for (int j = 0; j < 6; ++j) {
                st0[j] = bfly3(hE0[j] + hsum(accA[j]));
                st1[j] = bfly3(hE1[j] + hsum(accB[j]));
            }

            if (g == 0) {     // stress = s_eq + (-s_neq)
                float* so0 = out + b0 * TD + t * DE;
                float* so1 = so0 + TD;
#pragma unroll
                for (int k = 0; k < DE; k += 2) {
                    *(float2*)(so0 + k) = make_float2(st0[k], st0[k + 1]);
                    *(float2*)(so1 + k) = make_float2(st1[k], st1[k + 1]);
                }
            }

            // xi -= DT * (-kinetics): scalar FFMA with immediate multiplier
#pragma unroll
            for (int j = 0; j < NIV; ++j) {
                xs0[j] = fmaf(red8(accA[6 + j]), -0.01f, xs0[j]);
                xs1[j] = fmaf(red8(accB[6 + j]), -0.01f, xs1[j]);
            }
        }
    }
}

extern "C" void kernel_launch(void* const* d_in, const int* in_sizes, int n_in,
                              void* d_out, int out_size) {
    const float* e    = (const float*)d_in[0];
    const float* edot = (const float*)d_in[1];
    const float* Eg   = (const float*)d_in[2];
    const float* nug  = (const float*)d_in[3];
    const float* We1  = (const float*)d_in[4];
    const float* be1  = (const float*)d_in[5];
    const float* We2  = (const float*)d_in[6];
    const float* Wd1  = (const float*)d_in[8];
    const float* bd1  = (const float*)d_in[9];
    const float* Wd2  = (const float*)d_in[10];
    const float* WE   = (const float*)d_in[12];
    const float* bE   = (const float*)d_in[13];
    const float* Wnu  = (const float*)d_in[14];
    const float* bnu  = (const float*)d_in[15];
    float* out = (float*)d_out;

    reset_ctr_kernel<<<1, 1>>>();
    visco_kernel<<<444, 128>>>(e, edot, Eg, nug, We1, be1, We2,
                               Wd1, bd1, Wd2, WE, bE, Wnu, bnu, out);
}

// round 9
// speedup vs baseline: 1.2151x; 1.2151x over previous
#include <cuda_runtime.h>
#include <cuda_bf16.h>

#define B_TOT 32768
#define T_LEN 200
#define DE    6
#define NIV   8
#define H     128
#define DIN   46
#define NPAIR (B_TOT/2)
#define UNITS 64
#define ROWF  36
#define GRP   8
#define UPG   8
#define TD    (T_LEN*DE)
#define RUNS  (NPAIR/4)

typedef unsigned long long ull;

__device__ unsigned g_run_ctr;

static __device__ __forceinline__ ull pk2(float lo, float hi) {
    ull r; asm("mov.b64 %0,{%1,%2};" : "=l"(r) : "f"(lo), "f"(hi)); return r;
}
static __device__ __forceinline__ void upk2(ull v, float& lo, float& hi) {
    asm("mov.b64 {%0,%1},%2;" : "=f"(lo), "=f"(hi) : "l"(v));
}
static __device__ __forceinline__ ull fma2(ull a, ull b, ull c) {
    ull d; asm("fma.rn.f32x2 %0,%1,%2,%3;" : "=l"(d) : "l"(a), "l"(b), "l"(c)); return d;
}
static __device__ __forceinline__ ull mul2(ull a, ull b) {
    ull d; asm("mul.rn.f32x2 %0,%1,%2;" : "=l"(d) : "l"(a), "l"(b)); return d;
}
static __device__ __forceinline__ ull add2(ull a, ull b) {
    ull d; asm("add.rn.f32x2 %0,%1,%2;" : "=l"(d) : "l"(a), "l"(b)); return d;
}
static __device__ __forceinline__ ull relu2(ull a) {
    float lo, hi; upk2(a, lo, hi);
    lo = fmaxf(lo, 0.f); hi = fmaxf(hi, 0.f);
    return pk2(lo, hi);
}
static __device__ __forceinline__ ull dupf(float v) { return pk2(v, v); }

static __device__ __forceinline__ float hsum(ull v) {
    float lo, hi; upk2(v, lo, hi); return lo + hi;
}
static __device__ __forceinline__ float bfly3(float s) {
    s += __shfl_xor_sync(0xFFFFFFFFu, s, 4);
    s += __shfl_xor_sync(0xFFFFFFFFu, s, 8);
    s += __shfl_xor_sync(0xFFFFFFFFu, s, 16);
    return s;
}
static __device__ __forceinline__ float red8(ull v) { return bfly3(hsum(v)); }

static __device__ __forceinline__ void mlp2(const float* __restrict__ tab, int g,
    const ull* __restrict__ i6a, const ull* __restrict__ i8a, ull Ea, ull nua,
    const ull* __restrict__ i6b, const ull* __restrict__ i8b, ull Eb, ull nub,
    ull* __restrict__ accA, ull* __restrict__ accB)
{
    const int base = g * UPG;
#pragma unroll
    for (int i = 0; i < UPG; ++i) {
        int uu = base + ((i + g) & (UPG - 1));   // stagger: conflict-free banks
        const ulonglong2* r = reinterpret_cast<const ulonglong2*>(tab + uu * ROWF);
        ulonglong2 r0 = r[0], r1 = r[1], r2 = r[2], r3 = r[3], r4 = r[4];
        ulonglong2 r5 = r[5], r6 = r[6], r7 = r[7], r8 = r[8];

        ull pa = fma2(r7.y, Ea, r7.x);  pa = fma2(r8.x, nua, pa);
        pa = fma2(r0.x, i6a[0], pa);    pa = fma2(r0.y, i6a[1], pa);
        pa = fma2(r1.x, i6a[2], pa);    pa = fma2(r1.y, i6a[3], pa);
        pa = fma2(r2.x, i6a[4], pa);    pa = fma2(r2.y, i6a[5], pa);
        ull qa = mul2(r3.x, i8a[0]);    qa = fma2(r3.y, i8a[1], qa);
        qa = fma2(r4.x, i8a[2], qa);    qa = fma2(r4.y, i8a[3], qa);
        qa = fma2(r5.x, i8a[4], qa);    qa = fma2(r5.y, i8a[5], qa);
        qa = fma2(r6.x, i8a[6], qa);    qa = fma2(r6.y, i8a[7], qa);
        ull ra = mul2(relu2(add2(pa, qa)), r8.y);

        ull pb = fma2(r7.y, Eb, r7.x);  pb = fma2(r8.x, nub, pb);
        pb = fma2(r0.x, i6b[0], pb);    pb = fma2(r0.y, i6b[1], pb);
        pb = fma2(r1.x, i6b[2], pb);    pb = fma2(r1.y, i6b[3], pb);
        pb = fma2(r2.x, i6b[4], pb);    pb = fma2(r2.y, i6b[5], pb);
        ull qb = mul2(r3.x, i8b[0]);    qb = fma2(r3.y, i8b[1], qb);
        qb = fma2(r4.x, i8b[2], qb);    qb = fma2(r4.y, i8b[3], qb);
        qb = fma2(r5.x, i8b[4], qb);    qb = fma2(r5.y, i8b[5], qb);
        qb = fma2(r6.x, i8b[6], qb);    qb = fma2(r6.y, i8b[7], qb);
        ull rb = mul2(relu2(add2(pb, qb)), r8.y);

        accA[0]  = fma2(r0.x, ra, accA[0]);   accB[0]  = fma2(r0.x, rb, accB[0]);
        accA[1]  = fma2(r0.y, ra, accA[1]);   accB[1]  = fma2(r0.y, rb, accB[1]);
        accA[2]  = fma2(r1.x, ra, accA[2]);   accB[2]  = fma2(r1.x, rb, accB[2]);
        accA[3]  = fma2(r1.y, ra, accA[3]);   accB[3]  = fma2(r1.y, rb, accB[3]);
        accA[4]  = fma2(r2.x, ra, accA[4]);   accB[4]  = fma2(r2.x, rb, accB[4]);
        accA[5]  = fma2(r2.y, ra, accA[5]);   accB[5]  = fma2(r2.y, rb, accB[5]);
        accA[6]  = fma2(r3.x, ra, accA[6]);   accB[6]  = fma2(r3.x, rb, accB[6]);
        accA[7]  = fma2(r3.y, ra, accA[7]);   accB[7]  = fma2(r3.y, rb, accB[7]);
        accA[8]  = fma2(r4.x, ra, accA[8]);   accB[8]  = fma2(r4.x, rb, accB[8]);
        accA[9]  = fma2(r4.y, ra, accA[9]);   accB[9]  = fma2(r4.y, rb, accB[9]);
        accA[10] = fma2(r5.x, ra, accA[10]);  accB[10] = fma2(r5.x, rb, accB[10]);
        accA[11] = fma2(r5.y, ra, accA[11]);  accB[11] = fma2(r5.y, rb, accB[11]);
        accA[12] = fma2(r6.x, ra, accA[12]);  accB[12] = fma2(r6.x, rb, accB[12]);
        accA[13] = fma2(r6.y, ra, accA[13]);  accB[13] = fma2(r6.y, rb, accB[13]);
    }
}

__global__ void reset_ctr_kernel() { g_run_ctr = 0u; }

__global__ void __launch_bounds__(128, 2) visco_kernel(
    const float* __restrict__ e,   const float* __restrict__ edot,
    const float* __restrict__ Eg,  const float* __restrict__ nug,
    const float* __restrict__ We1, const float* __restrict__ be1,
    const float* __restrict__ We2,
    const float* __restrict__ Wd1, const float* __restrict__ bd1,
    const float* __restrict__ Wd2,
    const float* __restrict__ WE,  const float* __restrict__ bE,
    const float* __restrict__ Wnu, const float* __restrict__ bnu,
    float* __restrict__ out)
{
    __shared__ __align__(16) float sE2[UNITS * ROWF];
    __shared__ __align__(16) float sD2[UNITS * ROWF];

    {   // build row-pair-interleaved derived tables (thread h builds row h of both)
        int h = threadIdx.x;
        int u = h >> 1, par = h & 1;
        float* dE = sE2 + u * ROWF + par;
        float* dD = sD2 + u * ROWF + par;

        const float* w1 = We1 + h * DIN;
#pragma unroll
        for (int j = 0; j < 14; ++j) dE[2 * j] = w1[j];
        float a = be1[h], bt = 0.f, gm = 0.f;
#pragma unroll
        for (int k = 0; k < 16; ++k) { float wm = w1[14 + k]; a += wm * bE[k];  bt += wm * WE[k]; }
#pragma unroll
        for (int k = 0; k < 16; ++k) { float wm = w1[30 + k]; a += wm * bnu[k]; gm += wm * Wnu[k]; }
        dE[28] = a; dE[30] = bt; dE[32] = gm;
        dE[34] = 2.f * (We2[h] + We2[H + h]);

        const float* w2 = Wd1 + h * DIN;
#pragma unroll
        for (int j = 0; j < 14; ++j) dD[2 * j] = -w2[j];
        a = bd1[h]; bt = 0.f; gm = 0.f;
#pragma unroll
        for (int k = 0; k < 16; ++k) { float wm = w2[14 + k]; a += wm * bE[k];  bt += wm * WE[k]; }
#pragma unroll
        for (int k = 0; k < 16; ++k) { float wm = w2[30 + k]; a += wm * bnu[k]; gm += wm * Wnu[k]; }
        dD[28] = a; dD[30] = bt; dD[32] = gm;
        dD[34] = 2.f * Wd2[h];
    }
    __syncthreads();

    const int lane = threadIdx.x & 31;
    const int pr   = lane & 3;                   // pair slot within warp
    const int g    = lane >> 2;                  // h-split group 0..7
    const ull SGN  = 0x8000000080000000ULL;

    for (;;) {
        unsigned run;
        if (lane == 0) run = atomicAdd(&g_run_ctr, 1u);
        run = __shfl_sync(0xFFFFFFFFu, run, 0);
        if (run >= RUNS) break;

        int p = (int)run * 4 + pr;
        size_t b0 = 2 * (size_t)p, b1 = b0 + 1;

        ull E0d  = dupf(Eg[b0]),  E1d  = dupf(Eg[b1]);
        ull nu0d = dupf(nug[b0]), nu1d = dupf(nug[b1]);

        const float* pe0 = e    + b0 * TD;
        const float* pe1 = pe0  + TD;
        const float* pd0 = edot + b0 * TD;
        const float* pd1 = pd0  + TD;
        float* so0 = out + b0 * TD;
        float* so1 = so0 + TD;
        float* xo0 = out + (size_t)B_TOT * TD + b0 * (size_t)(T_LEN * NIV);
        float* xo1 = xo0 + T_LEN * NIV;

        // xi as scalars (lo==hi invariant under the broadcast update)
        float xs0[NIV], xs1[NIV];
#pragma unroll
        for (int j = 0; j < NIV; ++j) { xs0[j] = 0.f; xs1[j] = 0.f; }

        float2 ea0 = *(const float2*)(pe0), ea1 = *(const float2*)(pe0 + 2), ea2 = *(const float2*)(pe0 + 4);
        float2 eb0 = *(const float2*)(pe1), eb1 = *(const float2*)(pe1 + 2), eb2 = *(const float2*)(pe1 + 4);
        float2 da0 = *(const float2*)(pd0), da1 = *(const float2*)(pd0 + 2), da2 = *(const float2*)(pd0 + 4);
        float2 db0 = *(const float2*)(pd1), db1 = *(const float2*)(pd1 + 2), db2 = *(const float2*)(pd1 + 4);

        for (int t = 0; t < T_LEN; ++t) {
            // ---- E-MLP inputs (raw e-buffers die here) ----
            ull et0[6] = { dupf(ea0.x), dupf(ea0.y), dupf(ea1.x), dupf(ea1.y), dupf(ea2.x), dupf(ea2.y) };
            ull et1[6] = { dupf(eb0.x), dupf(eb0.y), dupf(eb1.x), dupf(eb1.y), dupf(eb2.x), dupf(eb2.y) };
            ull xi0p[NIV], xi1p[NIV];
#pragma unroll
            for (int j = 0; j < NIV; ++j) { xi0p[j] = dupf(xs0[j]); xi1p[j] = dupf(xs1[j]); }

            if (g == 1) {     // xi output (state entering this step)
                int ox = t * NIV;
#pragma unroll
                for (int k = 0; k < NIV; k += 2) {
                    *(float2*)(xo0 + ox + k) = make_float2(xs0[k], xs0[k + 1]);
                    *(float2*)(xo1 + ox + k) = make_float2(xs1[k], xs1[k + 1]);
                }
            }

            ull accA[14], accB[14];
#pragma unroll
            for (int j = 0; j < 14; ++j) { accA[j] = 0ULL; accB[j] = 0ULL; }
            mlp2(sE2, g, et0, xi0p, E0d, nu0d, et1, xi1p, E1d, nu1d, accA, accB);

            // seq partials (scalar, no shuffles); d reduced + broadcast
            float hE0[6], hE1[6];
            ull d0[8], d1[8];
#pragma unroll
            for (int j = 0; j < 6; ++j) { hE0[j] = hsum(accA[j]); hE1[j] = hsum(accB[j]); }
#pragma unroll
            for (int j = 0; j < 8; ++j) { d0[j] = dupf(red8(accA[6 + j])); d1[j] = dupf(red8(accB[6 + j])); }

            // ---- D-MLP inputs (raw d-buffers die here) ----
            ull ed0[6] = { dupf(da0.x) ^ SGN, dupf(da0.y) ^ SGN, dupf(da1.x) ^ SGN,
                           dupf(da1.y) ^ SGN, dupf(da2.x) ^ SGN, dupf(da2.y) ^ SGN };
            ull ed1[6] = { dupf(db0.x) ^ SGN, dupf(db0.y) ^ SGN, dupf(db1.x) ^ SGN,
                           dupf(db1.y) ^ SGN, dupf(db2.x) ^ SGN, dupf(db2.y) ^ SGN };

            // prefetch next step (raw buffers now free; still well ahead of use)
            if (t + 1 < T_LEN) {
                int o = (t + 1) * DE;
                ea0 = *(const float2*)(pe0 + o); ea1 = *(const float2*)(pe0 + o + 2); ea2 = *(const float2*)(pe0 + o + 4);
                eb0 = *(const float2*)(pe1 + o); eb1 = *(const float2*)(pe1 + o + 2); eb2 = *(const float2*)(pe1 + o + 4);
                da0 = *(const float2*)(pd0 + o); da1 = *(const float2*)(pd0 + o + 2); da2 = *(const float2*)(pd0 + o + 4);
                db0 = *(const float2*)(pd1 + o); db1 = *(const float2*)(pd1 + o + 2); db2 = *(const float2*)(pd1 + o + 4);
            }

#pragma unroll
            for (int j = 0; j < 14; ++j) { accA[j] = 0ULL; accB[j] = 0ULL; }
            mlp2(sD2, g, ed0, d0, E0d, nu0d, ed1, d1, E1d, nu1d, accA, accB);

            // stress: single butterfly over combined E+D partials
            float st0[6], st1[6];
#pragma unroll
            for (int j = 0; j < 6; ++j) {
                st0[j] = bfly3(hE0[j] + hsum(accA[j]));
                st1[j] = bfly3(hE1[j] + hsum(accB[j]));
            }

            if (g == 0) {     // stress = s_eq + (-s_neq)
                int os = t * DE;
#pragma unroll
                for (int k = 0; k < DE; k += 2) {
                    *(float2*)(so0 + os + k) = make_float2(st0[k], st0[k + 1]);
                    *(float2*)(so1 + os + k) = make_float2(st1[k], st1[k + 1]);
                }
            }

            // xi update: scalar FFMA with immediate multiplier (acc = -kinetics)
#pragma unroll
            for (int j = 0; j < NIV; ++j) {
                xs0[j] = fmaf(red8(accA[6 + j]), -0.01f, xs0[j]);
                xs1[j] = fmaf(red8(accB[6 + j]), -0.01f, xs1[j]);
            }
        }
    }
}

extern "C" void kernel_launch(void* const* d_in, const int* in_sizes, int n_in,
                              void* d_out, int out_size) {
    const float* e    = (const float*)d_in[0];
    const float* edot = (const float*)d_in[1];
    const float* Eg   = (const float*)d_in[2];
    const float* nug  = (const float*)d_in[3];
    const float* We1  = (const float*)d_in[4];
    const float* be1  = (const float*)d_in[5];
    const float* We2  = (const float*)d_in[6];
    const float* Wd1  = (const float*)d_in[8];
    const float* bd1  = (const float*)d_in[9];
    const float* Wd2  = (const float*)d_in[10];
    const float* WE   = (const float*)d_in[12];
    const float* bE   = (const float*)d_in[13];
    const float* Wnu  = (const float*)d_in[14];
    const float* bnu  = (const float*)d_in[15];
    float* out = (float*)d_out;

    reset_ctr_kernel<<<1, 1>>>();
    visco_kernel<<<296, 128>>>(e, edot, Eg, nug, We1, be1, We2,
                               Wd1, bd1, Wd2, WE, bE, Wnu, bnu, out);
}